// round 3
// baseline (speedup 1.0000x reference)
#include <cuda_runtime.h>

// out[b,o] = tanh( sum_{j<3} tanh(x[b]·w_in[:,j] - thr_h[j]) * w_ho[j,o] + C_o - 0.5 )
// C_o = sum_{j=3..63} tanh(-thr_h[j]) * w_ho[j,o]
//
// HBM-bound: stream x (128 MB) exactly once. w_in register-cached per persistent
// block (48 regs/thread) so there is no per-row L2 amplification.
// s_part is parity double-buffered -> exactly ONE __syncthreads per row.

#define NTHREADS 256
#define NBLOCKS  444          // 148 SMs * 3 resident blocks
#define BATCH_N  8192
#define DIM_N    4096
#define OUT_N    8

__global__ void __launch_bounds__(NTHREADS, 3)
enn_kernel(const float* __restrict__ x,
           const float* __restrict__ w_in,
           const float* __restrict__ w_ho,
           const float* __restrict__ thr_h,
           float* __restrict__ out)
{
    __shared__ float s_part[2][3][8]; // [parity][hidden j][warp]
    __shared__ float s_c[OUT_N];      // C_o - 0.5
    __shared__ float s_who[3][OUT_N];
    __shared__ float s_thr[3];

    const int t    = threadIdx.x;
    const int lane = t & 31;
    const int warp = t >> 5;

    // ---- one-time per-block prologue (cheap vs ~18 rows of streaming) ----
    if (t < 24) s_who[t / 8][t % 8] = w_ho[t];          // w_ho rows 0..2
    if (t < 3)  s_thr[t] = thr_h[t];
    if (t < OUT_N) {
        float c = -0.5f;
        #pragma unroll 1
        for (int j = 3; j < 64; j++)
            c = fmaf(tanhf(-thr_h[j]), w_ho[j * OUT_N + t], c);
        s_c[t] = c;
    }

    // ---- register-cache w_in: thread t owns float4-chunks {t, t+256, t+512, t+768}
    // chunk f covers dims 4f..4f+3 -> 12 consecutive w_in floats at index 12f
    // (byte offset 48f: always 16B aligned).
    float4 w[4][3];
    #pragma unroll
    for (int k = 0; k < 4; k++) {
        const int f = t + k * NTHREADS;
        const float4* wp = reinterpret_cast<const float4*>(w_in + 12 * f);
        w[k][0] = wp[0];
        w[k][1] = wp[1];
        w[k][2] = wp[2];
    }
    __syncthreads();

    int parity = 0;
    for (int row = blockIdx.x; row < BATCH_N; row += gridDim.x, parity ^= 1) {
        const float4* xr = reinterpret_cast<const float4*>(x + (size_t)row * DIM_N);

        float a0 = 0.f, a1 = 0.f, a2 = 0.f;
        #pragma unroll
        for (int k = 0; k < 4; k++) {
            const float4 xv = xr[t + k * NTHREADS];     // coalesced LDG.128
            // layout: W0=(d0j0,d0j1,d0j2,d1j0) W1=(d1j1,d1j2,d2j0,d2j1) W2=(d2j2,d3j0,d3j1,d3j2)
            a0 = fmaf(xv.x, w[k][0].x, a0);
            a0 = fmaf(xv.y, w[k][0].w, a0);
            a0 = fmaf(xv.z, w[k][1].z, a0);
            a0 = fmaf(xv.w, w[k][2].y, a0);

            a1 = fmaf(xv.x, w[k][0].y, a1);
            a1 = fmaf(xv.y, w[k][1].x, a1);
            a1 = fmaf(xv.z, w[k][1].w, a1);
            a1 = fmaf(xv.w, w[k][2].z, a1);

            a2 = fmaf(xv.x, w[k][0].z, a2);
            a2 = fmaf(xv.y, w[k][1].y, a2);
            a2 = fmaf(xv.z, w[k][2].x, a2);
            a2 = fmaf(xv.w, w[k][2].w, a2);
        }

        // warp tree-reduce the 3 partial dots
        #pragma unroll
        for (int off = 16; off > 0; off >>= 1) {
            a0 += __shfl_xor_sync(0xFFFFFFFFu, a0, off);
            a1 += __shfl_xor_sync(0xFFFFFFFFu, a1, off);
            a2 += __shfl_xor_sync(0xFFFFFFFFu, a2, off);
        }
        if (lane == 0) {
            s_part[parity][0][warp] = a0;
            s_part[parity][1][warp] = a1;
            s_part[parity][2][warp] = a2;
        }
        __syncthreads();   // single barrier: orders this row's writes before reads;
                           // next row writes the OTHER parity buffer, so no WAR hazard.

        if (t < OUT_N) {
            float s0 = 0.f, s1 = 0.f, s2 = 0.f;
            #pragma unroll
            for (int wv = 0; wv < 8; wv++) {
                s0 += s_part[parity][0][wv];
                s1 += s_part[parity][1][wv];
                s2 += s_part[parity][2][wv];
            }
            const float t0 = tanhf(s0 - s_thr[0]);
            const float t1 = tanhf(s1 - s_thr[1]);
            const float t2 = tanhf(s2 - s_thr[2]);
            float v = s_c[t];
            v = fmaf(t0, s_who[0][t], v);
            v = fmaf(t1, s_who[1][t], v);
            v = fmaf(t2, s_who[2][t], v);
            out[row * OUT_N + t] = tanhf(v);
        }
    }
}

extern "C" void kernel_launch(void* const* d_in, const int* in_sizes, int n_in,
                              void* d_out, int out_size)
{
    const float* x     = (const float*)d_in[0];   // [8192, 4096]
    const float* w_in  = (const float*)d_in[1];   // [4096, 3]
    const float* w_ho  = (const float*)d_in[2];   // [64, 8]
    const float* thr_h = (const float*)d_in[3];   // [64]
    float* out = (float*)d_out;                   // [8192, 8]

    enn_kernel<<<NBLOCKS, NTHREADS>>>(x, w_in, w_ho, thr_h, out);
}